// round 13
// baseline (speedup 1.0000x reference)
#include <cuda_runtime.h>
#include <cuda_fp16.h>
#include <math.h>
#include <stdint.h>

// Problem constants
#define BATCH   64
#define SEQ     256
#define NTOK    16384      // BATCH*SEQ
#define VOCAB   16
#define DMODEL  512
#define DFF     2048
#define NLAYER  6
#define NHEAD   8
#define DHEAD   64
#define DLAT    256
#define SD      131072     // SEQ*DMODEL

typedef __half fp16;

// ---------------- scratch (static __device__ — allocation-free) ----------------
__device__ float g_X    [NTOK * DMODEL];
__device__ fp16  g_QKVh [NTOK * 3 * DMODEL];
__device__ fp16  g_Xh   [NTOK * DMODEL];
__device__ fp16  g_Oh   [NTOK * DMODEL];
__device__ fp16  g_Hh   [NTOK * DFF];
__device__ fp16  g_Wq   [NLAYER * 3 * DMODEL * DMODEL];
__device__ fp16  g_Wo   [NLAYER * DMODEL * DMODEL];
__device__ fp16  g_W1   [NLAYER * DFF * DMODEL];
__device__ fp16  g_W2   [NLAYER * DMODEL * DFF];
__device__ float g_LP   [64 * BATCH * DLAT];
__device__ float g_MEM  [BATCH * DLAT];

// ---------------- helpers ----------------
__device__ __forceinline__ unsigned long long pack2(float lo, float hi) {
    unsigned long long r;
    asm("mov.b64 %0, {%1,%2};" : "=l"(r) : "f"(lo), "f"(hi));
    return r;
}
__device__ __forceinline__ void fma2(unsigned long long& d, unsigned long long a, unsigned long long b) {
    asm("fma.rn.f32x2 %0, %1, %2, %0;" : "+l"(d) : "l"(a), "l"(b));
}
__device__ __forceinline__ float2 unpack2(unsigned long long v) {
    float2 f;
    asm("mov.b64 {%0,%1}, %2;" : "=f"(f.x), "=f"(f.y) : "l"(v));
    return f;
}
__device__ __forceinline__ float warpSum(float v) {
    #pragma unroll
    for (int o = 16; o > 0; o >>= 1) v += __shfl_xor_sync(0xffffffffu, v, o);
    return v;
}
__device__ __forceinline__ uint32_t smem_u32(const void* p) {
    uint32_t a;
    asm("{ .reg .u64 t; cvta.to.shared.u64 t, %1; cvt.u32.u64 %0, t; }" : "=r"(a) : "l"(p));
    return a;
}

// ---------------- mma.sync / ldmatrix / cp.async wrappers --------------------
__device__ __forceinline__ void ldmx4(uint32_t* r, uint32_t addr) {
    asm volatile("ldmatrix.sync.aligned.m8n8.x4.shared.b16 {%0,%1,%2,%3}, [%4];"
        : "=r"(r[0]), "=r"(r[1]), "=r"(r[2]), "=r"(r[3]) : "r"(addr));
}
__device__ __forceinline__ void ldmx2(uint32_t* r, uint32_t addr) {
    asm volatile("ldmatrix.sync.aligned.m8n8.x2.shared.b16 {%0,%1}, [%2];"
        : "=r"(r[0]), "=r"(r[1]) : "r"(addr));
}
__device__ __forceinline__ void mma_f16(float* d, const uint32_t* a, const uint32_t* b) {
    asm volatile("mma.sync.aligned.m16n8k16.row.col.f32.f16.f16.f32 "
        "{%0,%1,%2,%3}, {%4,%5,%6,%7}, {%8,%9}, {%0,%1,%2,%3};"
        : "+f"(d[0]), "+f"(d[1]), "+f"(d[2]), "+f"(d[3])
        : "r"(a[0]), "r"(a[1]), "r"(a[2]), "r"(a[3]), "r"(b[0]), "r"(b[1]));
}
__device__ __forceinline__ void cp_async16(uint32_t saddr, const void* gaddr) {
    asm volatile("cp.async.cg.shared.global [%0], [%1], 16;" :: "r"(saddr), "l"(gaddr));
}
__device__ __forceinline__ void cp_commit() {
    asm volatile("cp.async.commit_group;");
}
template <int N>
__device__ __forceinline__ void cp_wait() {
    asm volatile("cp.async.wait_group %0;" :: "n"(N));
}

// ---------------- weight fp16 convert (all 4 in one launch) ------------------
__global__ void conv4_kernel(const float* __restrict__ s0, fp16* __restrict__ d0, int n0,
                             const float* __restrict__ s1, fp16* __restrict__ d1, int n1,
                             const float* __restrict__ s2, fp16* __restrict__ d2, int n2,
                             const float* __restrict__ s3, fp16* __restrict__ d3, int n3) {
    int i = blockIdx.x * 256 + threadIdx.x;
    if (i < n0) { d0[i] = __float2half_rn(s0[i]); return; }
    i -= n0;
    if (i < n1) { d1[i] = __float2half_rn(s1[i]); return; }
    i -= n1;
    if (i < n2) { d2[i] = __float2half_rn(s2[i]); return; }
    i -= n2;
    if (i < n3) { d3[i] = __float2half_rn(s3[i]); }
}

// ---------------- embedding + posenc (+ fp16 round) ----------------
__global__ void embed_kernel(const float* __restrict__ src,
                             const float* __restrict__ ew,
                             const float* __restrict__ eb,
                             float* __restrict__ X,
                             fp16* __restrict__ Xh) {
    __shared__ float sv[VOCAB];
    const int t   = blockIdx.x;
    const int tid = threadIdx.x;              // 128
    if (tid < VOCAB) sv[tid] = src[(size_t)t * VOCAB + tid];
    __syncthreads();
    const int s = t & (SEQ - 1);
    const float c = 0.017988946f;             // log(10000)/512
    #pragma unroll
    for (int r = 0; r < 4; r++) {
        const int d = tid + r * 128;
        float acc = eb[d];
        #pragma unroll
        for (int v = 0; v < VOCAB; v++) acc += sv[v] * ew[d * VOCAB + v];
        const int i2 = d & ~1;
        const float den = expf(-(float)i2 * c);
        const float arg = (float)s * den;
        const float pe = (d & 1) ? cosf(arg) : sinf(arg);
        const float y = acc + pe;
        const size_t o = (size_t)t * DMODEL + d;
        X[o] = y;
        Xh[o] = __float2half_rn(y);
    }
}

// ---------------- HMMA GEMM: C[M,N] = A[M,K] @ W[N,K]^T + bias (fp16 in)
// 128x128x32 CTA tile, 8 warps (2Mx4N, warp tile 64x32), cp.async double buffer.
// OUT=1: (C+bias) -> fp16 Ch.  OUT=2: relu -> fp16 Ch.
template <int OUT>
__global__ __launch_bounds__(256, 2)
void gemm_tc(const fp16* __restrict__ A, const fp16* __restrict__ W,
             const float* __restrict__ bias, fp16* __restrict__ Ch,
             int M, int N, int K) {
    extern __shared__ char smraw[];
    const uint32_t sbase = smem_u32(smraw);
    const int tid  = threadIdx.x;
    const int lane = tid & 31;
    const int wid  = tid >> 5;
    const int wm   = wid >> 2;          // 0..1
    const int wn   = wid & 3;           // 0..3
    const int mBase = blockIdx.y * 128;
    const int nBase = blockIdx.x * 128;

    uint32_t aA[2], aB[2];
    {
        const int rowA = wm * 64 + (lane & 7) + ((lane >> 3) & 1) * 8;
        const int rowB = wn * 32 + (lane & 7);
        #pragma unroll
        for (int ks = 0; ks < 2; ks++) {
            const int cA = (ks * 16 + (lane >> 4) * 8) >> 3;
            const int cB = (ks * 16 + ((lane >> 3) & 1) * 8) >> 3;
            aA[ks] = rowA * 64 + ((cA ^ ((rowA >> 1) & 3)) << 4);
            aB[ks] = rowB * 64 + ((cB ^ ((rowB >> 1) & 3)) << 4);
        }
    }

    float acc[4][4][4];
    #pragma unroll
    for (int i = 0; i < 4; i++)
        #pragma unroll
        for (int j = 0; j < 4; j++)
            #pragma unroll
            for (int k = 0; k < 4; k++) acc[i][j][k] = 0.f;

    const int NC = K >> 5;

    auto load_chunk = [&](uint32_t sbuf, int k0) {
        #pragma unroll
        for (int t = 0; t < 2; t++) {
            const int idx = tid + t * 256;
            const int r = idx >> 2, c = idx & 3;
            const uint32_t so = r * 64 + ((c ^ ((r >> 1) & 3)) << 4);
            const size_t ga = (size_t)(mBase + r) * K + k0 + c * 8;
            const size_t gw = (size_t)(nBase + r) * K + k0 + c * 8;
            cp_async16(sbuf + so,        A + ga);
            cp_async16(sbuf + 8192 + so, W + gw);
        }
    };

    load_chunk(sbase, 0);
    cp_commit();

    for (int kc = 0; kc < NC; kc++) {
        const uint32_t cbuf = sbase + (kc & 1) * 16384;
        if (kc + 1 < NC) {
            load_chunk(sbase + ((kc + 1) & 1) * 16384, (kc + 1) * 32);
            cp_commit();
            cp_wait<1>();
        } else {
            cp_wait<0>();
        }
        __syncthreads();

        #pragma unroll
        for (int ks = 0; ks < 2; ks++) {
            uint32_t Ah[4][4], Bh[4][2];
            #pragma unroll
            for (int mt = 0; mt < 4; mt++)
                ldmx4(Ah[mt], cbuf + aA[ks] + mt * 1024);
            #pragma unroll
            for (int nt = 0; nt < 4; nt++)
                ldmx2(Bh[nt], cbuf + 8192 + aB[ks] + nt * 512);
            #pragma unroll
            for (int mt = 0; mt < 4; mt++)
                #pragma unroll
                for (int nt = 0; nt < 4; nt++)
                    mma_f16(acc[mt][nt], Ah[mt], Bh[nt]);
        }
        __syncthreads();
    }

    const int r0 = mBase + wm * 64 + (lane >> 2);
    const int c0 = nBase + wn * 32 + (lane & 3) * 2;
    #pragma unroll
    for (int mt = 0; mt < 4; mt++) {
        #pragma unroll
        for (int nt = 0; nt < 4; nt++) {
            const int r = r0 + mt * 16;
            const int c = c0 + nt * 8;
            const float b0 = __ldg(bias + c), b1 = __ldg(bias + c + 1);
            float v0 = acc[mt][nt][0] + b0;
            float v1 = acc[mt][nt][1] + b1;
            float v2 = acc[mt][nt][2] + b0;
            float v3 = acc[mt][nt][3] + b1;
            if (OUT == 2) {
                v0 = fmaxf(v0, 0.f); v1 = fmaxf(v1, 0.f);
                v2 = fmaxf(v2, 0.f); v3 = fmaxf(v3, 0.f);
            }
            *(__half2*)(Ch + (size_t)r * N + c)       = __floats2half2_rn(v0, v1);
            *(__half2*)(Ch + (size_t)(r + 8) * N + c) = __floats2half2_rn(v2, v3);
        }
    }
}

// ---------------- fused GEMM + residual + LayerNorm (N = 512) ----------------
// C = A[M,K] @ W[512,K]^T + bias;  X = LN(X + C)*gamma + beta; Xh = fp16(X).
// CTA tile 32x512: 8 warps, warp tile 32x64 (2 m-frags x 8 n-frags).
// CTA owns complete rows -> row-wise LN reduction in-CTA.
#define GLN_STAGE 34816           // W 32KB + A 2KB
#define GLN_SMEM  (2 * GLN_STAGE)

__global__ __launch_bounds__(256)
void gemm_ln(const fp16* __restrict__ A, const fp16* __restrict__ W,
             const float* __restrict__ bias,
             const float* __restrict__ gamma, const float* __restrict__ beta,
             float* __restrict__ X, fp16* __restrict__ Xh, int K) {
    extern __shared__ char smraw[];
    __shared__ float sRed[2][32][8];
    const uint32_t sbase = smem_u32(smraw);
    const int tid  = threadIdx.x;
    const int lane = tid & 31;
    const int wid  = tid >> 5;          // 0..7, owns cols wid*64..wid*64+63
    const int mBase = blockIdx.x * 32;

    uint32_t aA[2], aB[2];
    {
        const int rowA = (lane & 7) + ((lane >> 3) & 1) * 8;
        const int rowB = wid * 64 + (lane & 7);
        #pragma unroll
        for (int ks = 0; ks < 2; ks++) {
            const int cA = (ks * 16 + (lane >> 4) * 8) >> 3;
            const int cB = (ks * 16 + ((lane >> 3) & 1) * 8) >> 3;
            aA[ks] = rowA * 64 + ((cA ^ ((rowA >> 1) & 3)) << 4);
            aB[ks] = rowB * 64 + ((cB ^ ((rowB >> 1) & 3)) << 4);
        }
    }

    float acc[2][8][4];
    #pragma unroll
    for (int i = 0; i < 2; i++)
        #pragma unroll
        for (int j = 0; j < 8; j++)
            #pragma unroll
            for (int k = 0; k < 4; k++) acc[i][j][k] = 0.f;

    const int NC = K >> 5;

    // loader: W 512 rows x 4 x 16B (2048 tasks), A 32 rows x 4 x 16B (128 tasks)
    auto load_chunk = [&](uint32_t sbuf, int k0) {
        #pragma unroll
        for (int t = 0; t < 8; t++) {
            const int idx = tid + t * 256;
            const int r = idx >> 2, c = idx & 3;
            const uint32_t so = r * 64 + ((c ^ ((r >> 1) & 3)) << 4);
            cp_async16(sbuf + so, W + (size_t)r * K + k0 + c * 8);
        }
        if (tid < 128) {
            const int r = tid >> 2, c = tid & 3;
            const uint32_t so = r * 64 + ((c ^ ((r >> 1) & 3)) << 4);
            cp_async16(sbuf + 32768 + so, A + (size_t)(mBase + r) * K + k0 + c * 8);
        }
    };

    load_chunk(sbase, 0);
    cp_commit();

    for (int kc = 0; kc < NC; kc++) {
        const uint32_t cbuf = sbase + (kc & 1) * GLN_STAGE;
        if (kc + 1 < NC) {
            load_chunk(sbase + ((kc + 1) & 1) * GLN_STAGE, (kc + 1) * 32);
            cp_commit();
            cp_wait<1>();
        } else {
            cp_wait<0>();
        }
        __syncthreads();

        #pragma unroll
        for (int ks = 0; ks < 2; ks++) {
            uint32_t Ah[2][4], Bh[8][2];
            #pragma unroll
            for (int mt = 0; mt < 2; mt++)
                ldmx4(Ah[mt], cbuf + 32768 + aA[ks] + mt * 1024);
            #pragma unroll
            for (int nt = 0; nt < 8; nt++)
                ldmx2(Bh[nt], cbuf + aB[ks] + nt * 512);
            #pragma unroll
            for (int mt = 0; mt < 2; mt++)
                #pragma unroll
                for (int nt = 0; nt < 8; nt++)
                    mma_f16(acc[mt][nt], Ah[mt], Bh[nt]);
        }
        __syncthreads();
    }

    // ---- epilogue: y = acc + bias + X; row stats; LN; write X/Xh ----
    // thread's rows: mt*16 + rh*8 + (lane>>2); cols: wid*64 + nt*8 + (lane&3)*2
    #pragma unroll
    for (int mt = 0; mt < 2; mt++) {
        #pragma unroll
        for (int rh = 0; rh < 2; rh++) {
            const int rl = mt * 16 + rh * 8 + (lane >> 2);
            const size_t gr = (size_t)(mBase + rl) * DMODEL;
            float s = 0.f, q = 0.f;
            #pragma unroll
            for (int nt = 0; nt < 8; nt++) {
                const int c = wid * 64 + nt * 8 + (lane & 3) * 2;
                const float2 xv = *(const float2*)(X + gr + c);
                const float y0 = acc[mt][nt][rh * 2]     + __ldg(bias + c)     + xv.x;
                const float y1 = acc[mt][nt][rh * 2 + 1] + __ldg(bias + c + 1) + xv.y;
                acc[mt][nt][rh * 2]     = y0;
                acc[mt][nt][rh * 2 + 1] = y1;
                s += y0 + y1;
                q += y0 * y0 + y1 * y1;
            }
            s += __shfl_xor_sync(0xffffffffu, s, 1);
            s += __shfl_xor_sync(0xffffffffu, s, 2);
            q += __shfl_xor_sync(0xffffffffu, q, 1);
            q += __shfl_xor_sync(0xffffffffu, q, 2);
            if ((lane & 3) == 0) {
                sRed[0][rl][wid] = s;
                sRed[1][rl][wid] = q;
            }
        }
    }
    __syncthreads();
    #pragma unroll
    for (int mt = 0; mt < 2; mt++) {
        #pragma unroll
        for (int rh = 0; rh < 2; rh++) {
            const int rl = mt * 16 + rh * 8 + (lane >> 2);
            const size_t gr = (size_t)(mBase + rl) * DMODEL;
            float tS = 0.f, tQ = 0.f;
            #pragma unroll
            for (int w = 0; w < 8; w++) { tS += sRed[0][rl][w]; tQ += sRed[1][rl][w]; }
            const float mean = tS * (1.f / DMODEL);
            const float var  = tQ * (1.f / DMODEL) - mean * mean;
            const float inv  = rsqrtf(var + 1e-5f);
            #pragma unroll
            for (int nt = 0; nt < 8; nt++) {
                const int c = wid * 64 + nt * 8 + (lane & 3) * 2;
                const float z0 = (acc[mt][nt][rh * 2]     - mean) * inv * __ldg(gamma + c)     + __ldg(beta + c);
                const float z1 = (acc[mt][nt][rh * 2 + 1] - mean) * inv * __ldg(gamma + c + 1) + __ldg(beta + c + 1);
                *(float2*)(X + gr + c) = make_float2(z0, z1);
                *(__half2*)(Xh + gr + c) = __floats2half2_rn(z0, z1);
            }
        }
    }
}

// ---------------- FA2-style HMMA attention -----------------------------------
#define ATTN_SMEM ((256 * 72 + 64 * 264) * 2)

__global__ __launch_bounds__(256, 1)
void attn_mma(const fp16* __restrict__ QKVh, fp16* __restrict__ Oh) {
    extern __shared__ fp16 smh[];
    fp16* Ks = smh;               // [256][72]
    fp16* Vt = smh + 256 * 72;    // [64][264]
    const int h = blockIdx.x, b = blockIdx.y;
    const int tid = threadIdx.x, lane = tid & 31, wid = tid >> 5;
    const fp16* base = QKVh + (size_t)b * SEQ * 1536;

    {
        const fp16* src = base + (size_t)tid * 1536 + 512 + h * 64;
        fp16* dst = Ks + tid * 72;
        #pragma unroll
        for (int i = 0; i < 8; i++)
            *(uint4*)(dst + i * 8) = *(const uint4*)(src + i * 8);
    }
    {
        const fp16* src = base + (size_t)tid * 1536 + 1024 + h * 64;
        #pragma unroll
        for (int i = 0; i < 32; i++) {
            const __half2 v = *(const __half2*)(src + 2 * i);
            Vt[(2 * i) * 264 + tid]     = __low2half(v);
            Vt[(2 * i + 1) * 264 + tid] = __high2half(v);
        }
    }
    __syncthreads();

    const uint32_t ksb = smem_u32(Ks);
    const uint32_t vtb = smem_u32(Vt);

    uint32_t qf[2][4][4];
    #pragma unroll
    for (int mt = 0; mt < 2; mt++)
        #pragma unroll
        for (int ks = 0; ks < 4; ks++) {
            const fp16* qp = base + (size_t)(wid * 32 + mt * 16 + (lane >> 2)) * 1536
                             + h * 64 + ks * 16 + (lane & 3) * 2;
            qf[mt][ks][0] = *(const uint32_t*)(qp);
            qf[mt][ks][1] = *(const uint32_t*)(qp + 8 * 1536);
            qf[mt][ks][2] = *(const uint32_t*)(qp + 8);
            qf[mt][ks][3] = *(const uint32_t*)(qp + 8 * 1536 + 8);
        }

    float oacc[2][8][4];
    #pragma unroll
    for (int mt = 0; mt < 2; mt++)
        #pragma unroll
        for (int nt = 0; nt < 8; nt++)
            #pragma unroll
            for (int k = 0; k < 4; k++) oacc[mt][nt][k] = 0.f;
    float m[2][2] = {{-1e30f, -1e30f}, {-1e30f, -1e30f}};
    float l[2][2] = {{0.f, 0.f}, {0.f, 0.f}};

    for (int kc = 0; kc < 16; kc++) {
        float cs[2][2][4];
        #pragma unroll
        for (int mt = 0; mt < 2; mt++)
            #pragma unroll
            for (int nt2 = 0; nt2 < 2; nt2++)
                #pragma unroll
                for (int k = 0; k < 4; k++) cs[mt][nt2][k] = 0.f;

        #pragma unroll
        for (int ks = 0; ks < 4; ks++) {
            uint32_t bk[2][2];
            #pragma unroll
            for (int nt2 = 0; nt2 < 2; nt2++)
                ldmx2(bk[nt2], ksb + ((kc * 16 + nt2 * 8 + (lane & 7)) * 72
                                      + ks * 16 + ((lane >> 3) & 1) * 8) * 2);
            #pragma unroll
            for (int mt = 0; mt < 2; mt++)
                #pragma unroll
                for (int nt2 = 0; nt2 < 2; nt2++)
                    mma_f16(cs[mt][nt2], qf[mt][ks], bk[nt2]);
        }

        uint32_t pf[2][4];
        #pragma unroll
        for (int mt = 0; mt < 2; mt++)
            #pragma unroll
            for (int rh = 0; rh < 2; rh++) {
                const float v0 = cs[mt][0][rh * 2]     * 0.125f;
                const float v1 = cs[mt][0][rh * 2 + 1] * 0.125f;
                const float v2 = cs[mt][1][rh * 2]     * 0.125f;
                const float v3 = cs[mt][1][rh * 2 + 1] * 0.125f;
                float mx = fmaxf(fmaxf(v0, v1), fmaxf(v2, v3));
                mx = fmaxf(mx, __shfl_xor_sync(0xffffffffu, mx, 1));
                mx = fmaxf(mx, __shfl_xor_sync(0xffffffffu, mx, 2));
                const float mnew = fmaxf(m[mt][rh], mx);
                const float corr = __expf(m[mt][rh] - mnew);
                m[mt][rh] = mnew;
                const float p0 = __expf(v0 - mnew);
                const float p1 = __expf(v1 - mnew);
                const float p2 = __expf(v2 - mnew);
                const float p3 = __expf(v3 - mnew);
                float ls = (p0 + p1) + (p2 + p3);
                ls += __shfl_xor_sync(0xffffffffu, ls, 1);
                ls += __shfl_xor_sync(0xffffffffu, ls, 2);
                l[mt][rh] = l[mt][rh] * corr + ls;
                #pragma unroll
                for (int nt = 0; nt < 8; nt++) {
                    oacc[mt][nt][rh * 2]     *= corr;
                    oacc[mt][nt][rh * 2 + 1] *= corr;
                }
                const __half2 ph0 = __floats2half2_rn(p0, p1);
                const __half2 ph1 = __floats2half2_rn(p2, p3);
                pf[mt][rh]     = *(const uint32_t*)&ph0;
                pf[mt][rh + 2] = *(const uint32_t*)&ph1;
            }

        #pragma unroll
        for (int nt = 0; nt < 8; nt++) {
            uint32_t bv[2];
            ldmx2(bv, vtb + ((nt * 8 + (lane & 7)) * 264
                             + kc * 16 + ((lane >> 3) & 1) * 8) * 2);
            mma_f16(oacc[0][nt], pf[0], bv);
            mma_f16(oacc[1][nt], pf[1], bv);
        }
    }

    #pragma unroll
    for (int mt = 0; mt < 2; mt++) {
        const float i0 = 1.f / l[mt][0];
        const float i1 = 1.f / l[mt][1];
        const int r = b * SEQ + wid * 32 + mt * 16 + (lane >> 2);
        #pragma unroll
        for (int nt = 0; nt < 8; nt++) {
            const int c = h * 64 + nt * 8 + (lane & 3) * 2;
            *(__half2*)(Oh + (size_t)r * DMODEL + c) =
                __floats2half2_rn(oacc[mt][nt][0] * i0, oacc[mt][nt][1] * i0);
            *(__half2*)(Oh + (size_t)(r + 8) * DMODEL + c) =
                __floats2half2_rn(oacc[mt][nt][2] * i1, oacc[mt][nt][3] * i1);
        }
    }
}

// ---------------- latent GEMM split-K (fp32, f32x2) --------------------------
__global__ __launch_bounds__(256, 2)
void latent_partial(const float* __restrict__ Xf, const float* __restrict__ Wl,
                    float* __restrict__ P) {
    __shared__ float As[16][64];
    __shared__ float Ws[16][64];
    const int tid = threadIdx.x;
    const int tx = tid & 15, ty = tid >> 4;
    const int nBase = blockIdx.x * 64;
    const int kBase = blockIdx.y * 2048;
    const int lr = tid >> 2;
    const int lk = (tid & 3) * 4;

    unsigned long long acc[4][2];
    #pragma unroll
    for (int i = 0; i < 4; i++) { acc[i][0] = 0ULL; acc[i][1] = 0ULL; }

    const float* Ab = Xf + (size_t)lr * SD + kBase;
    const float* Wb = Wl + (size_t)(nBase + lr) * SD + kBase;

    for (int k0 = 0; k0 < 2048; k0 += 16) {
        float4 a = *(const float4*)(Ab + k0 + lk);
        float4 w = *(const float4*)(Wb + k0 + lk);
        __syncthreads();
        As[lk + 0][lr] = a.x; As[lk + 1][lr] = a.y; As[lk + 2][lr] = a.z; As[lk + 3][lr] = a.w;
        Ws[lk + 0][lr] = w.x; Ws[lk + 1][lr] = w.y; Ws[lk + 2][lr] = w.z; Ws[lk + 3][lr] = w.w;
        __syncthreads();
        #pragma unroll
        for (int kk = 0; kk < 16; kk++) {
            float a4[4];
            #pragma unroll
            for (int i = 0; i < 4; i++) a4[i] = As[kk][ty * 4 + i];
            const unsigned long long* wrow = (const unsigned long long*)&Ws[kk][0];
            unsigned long long w2[2] = { wrow[tx * 2], wrow[tx * 2 + 1] };
            #pragma unroll
            for (int i = 0; i < 4; i++) {
                unsigned long long ad = pack2(a4[i], a4[i]);
                fma2(acc[i][0], ad, w2[0]);
                fma2(acc[i][1], ad, w2[1]);
            }
        }
    }
    #pragma unroll
    for (int i = 0; i < 4; i++) {
        const int bb = ty * 4 + i;
        #pragma unroll
        for (int j = 0; j < 2; j++) {
            float2 v = unpack2(acc[i][j]);
            const int n = nBase + tx * 4 + 2 * j;
            P[(size_t)blockIdx.y * (BATCH * DLAT) + bb * DLAT + n]     = v.x;
            P[(size_t)blockIdx.y * (BATCH * DLAT) + bb * DLAT + n + 1] = v.y;
        }
    }
}

__global__ void latent_reduce(const float* __restrict__ P, const float* __restrict__ lb,
                              float* __restrict__ mem) {
    const int idx = blockIdx.x * 256 + threadIdx.x;  // 16384
    float s = lb[idx & (DLAT - 1)];
    #pragma unroll 8
    for (int ks = 0; ks < 64; ks++) s += P[(size_t)ks * (BATCH * DLAT) + idx];
    mem[idx] = s;
}

__global__ void head_kernel(const float* __restrict__ mem, const float* __restrict__ hw,
                            const float* __restrict__ hb, float* __restrict__ out) {
    const int b = blockIdx.x;
    const int tid = threadIdx.x;  // 256
    float v = mem[b * DLAT + tid] * hw[tid];
    __shared__ float sS[8];
    const float ws = warpSum(v);
    if ((tid & 31) == 0) sS[tid >> 5] = ws;
    __syncthreads();
    if (tid == 0) {
        float t = 0.f;
        #pragma unroll
        for (int i = 0; i < 8; i++) t += sS[i];
        const float z = t + hb[0];
        out[b] = 1.f / (1.f + expf(-z));
    }
}

// ---------------- launch ----------------
#define GEMM_SMEM (2 * 16384)

extern "C" void kernel_launch(void* const* d_in, const int* in_sizes, int n_in,
                              void* d_out, int out_size) {
    const float* src    = (const float*)d_in[0];
    const float* emb_w  = (const float*)d_in[1];
    const float* emb_b  = (const float*)d_in[2];
    const float* qkv_w  = (const float*)d_in[3];
    const float* qkv_b  = (const float*)d_in[4];
    const float* out_w  = (const float*)d_in[5];
    const float* out_b  = (const float*)d_in[6];
    const float* ff1_w  = (const float*)d_in[7];
    const float* ff1_b  = (const float*)d_in[8];
    const float* ff2_w  = (const float*)d_in[9];
    const float* ff2_b  = (const float*)d_in[10];
    const float* ln1_g  = (const float*)d_in[11];
    const float* ln1_b  = (const float*)d_in[12];
    const float* ln2_g  = (const float*)d_in[13];
    const float* ln2_b  = (const float*)d_in[14];
    const float* lat_w  = (const float*)d_in[15];
    const float* lat_b  = (const float*)d_in[16];
    const float* head_w = (const float*)d_in[17];
    const float* head_b = (const float*)d_in[18];
    float* out = (float*)d_out;

    float *X, *P, *MEM;
    fp16 *QKVh, *Xh, *Oh, *Hh, *Wq, *Wo, *W1, *W2;
    cudaGetSymbolAddress((void**)&X,    g_X);
    cudaGetSymbolAddress((void**)&P,    g_LP);
    cudaGetSymbolAddress((void**)&MEM,  g_MEM);
    cudaGetSymbolAddress((void**)&QKVh, g_QKVh);
    cudaGetSymbolAddress((void**)&Xh,   g_Xh);
    cudaGetSymbolAddress((void**)&Oh,   g_Oh);
    cudaGetSymbolAddress((void**)&Hh,   g_Hh);
    cudaGetSymbolAddress((void**)&Wq,   g_Wq);
    cudaGetSymbolAddress((void**)&Wo,   g_Wo);
    cudaGetSymbolAddress((void**)&W1,   g_W1);
    cudaGetSymbolAddress((void**)&W2,   g_W2);

    cudaFuncSetAttribute(attn_mma,
                         cudaFuncAttributeMaxDynamicSharedMemorySize, ATTN_SMEM);
    cudaFuncSetAttribute(gemm_tc<1>,
                         cudaFuncAttributeMaxDynamicSharedMemorySize, GEMM_SMEM);
    cudaFuncSetAttribute(gemm_tc<2>,
                         cudaFuncAttributeMaxDynamicSharedMemorySize, GEMM_SMEM);
    cudaFuncSetAttribute(gemm_ln,
                         cudaFuncAttributeMaxDynamicSharedMemorySize, GLN_SMEM);

    // one-time-per-call weight converts (fp32 -> fp16), single launch
    {
        const int nq = NLAYER * 3 * DMODEL * DMODEL;
        const int no = NLAYER * DMODEL * DMODEL;
        const int n1 = NLAYER * DFF * DMODEL;
        const int n2 = NLAYER * DMODEL * DFF;
        const int ntot = nq + no + n1 + n2;
        conv4_kernel<<<(ntot + 255) / 256, 256>>>(qkv_w, Wq, nq, out_w, Wo, no,
                                                  ff1_w, W1, n1, ff2_w, W2, n2);
    }

    embed_kernel<<<NTOK, 128>>>(src, emb_w, emb_b, X, Xh);

    for (int l = 0; l < NLAYER; l++) {
        gemm_tc<1><<<dim3(12, 128), 256, GEMM_SMEM>>>(
            Xh, Wq + (size_t)l * 1536 * DMODEL,
            qkv_b + l * 1536, QKVh, NTOK, 1536, DMODEL);
        attn_mma<<<dim3(NHEAD, BATCH), 256, ATTN_SMEM>>>(QKVh, Oh);
        gemm_ln<<<NTOK / 32, 256, GLN_SMEM>>>(
            Oh, Wo + (size_t)l * DMODEL * DMODEL, out_b + l * DMODEL,
            ln1_g + l * DMODEL, ln1_b + l * DMODEL, X, Xh, DMODEL);
        gemm_tc<2><<<dim3(16, 128), 256, GEMM_SMEM>>>(
            Xh, W1 + (size_t)l * DFF * DMODEL,
            ff1_b + l * DFF, Hh, NTOK, DFF, DMODEL);
        gemm_ln<<<NTOK / 32, 256, GLN_SMEM>>>(
            Hh, W2 + (size_t)l * DMODEL * DFF, ff2_b + l * DMODEL,
            ln2_g + l * DMODEL, ln2_b + l * DMODEL, X, Xh, DFF);
    }

    latent_partial<<<dim3(4, 64), 256>>>(X, lat_w, P);
    latent_reduce<<<64, 256>>>(P, lat_b, MEM);
    head_kernel<<<BATCH, 256>>>(MEM, head_w, head_b, out);
}

// round 14
// speedup vs baseline: 1.1322x; 1.1322x over previous
#include <cuda_runtime.h>
#include <cuda_fp16.h>
#include <math.h>
#include <stdint.h>

// Problem constants
#define BATCH   64
#define SEQ     256
#define NTOK    16384      // BATCH*SEQ
#define VOCAB   16
#define DMODEL  512
#define DFF     2048
#define NLAYER  6
#define NHEAD   8
#define DHEAD   64
#define DLAT    256
#define SD      131072     // SEQ*DMODEL

typedef __half fp16;

// ---------------- scratch (static __device__ — allocation-free) ----------------
__device__ float g_X    [NTOK * DMODEL];
__device__ float g_PE   [SEQ * DMODEL];
__device__ fp16  g_QKVh [NTOK * 3 * DMODEL];
__device__ fp16  g_Xh   [NTOK * DMODEL];
__device__ fp16  g_Oh   [NTOK * DMODEL];
__device__ fp16  g_Th   [NTOK * DMODEL];
__device__ fp16  g_Hh   [NTOK * DFF];
__device__ fp16  g_Wq   [NLAYER * 3 * DMODEL * DMODEL];
__device__ fp16  g_Wo   [NLAYER * DMODEL * DMODEL];
__device__ fp16  g_W1   [NLAYER * DFF * DMODEL];
__device__ fp16  g_W2   [NLAYER * DMODEL * DFF];
__device__ float g_LP   [64 * BATCH * DLAT];
__device__ float g_MEM  [BATCH * DLAT];

// ---------------- helpers ----------------
__device__ __forceinline__ unsigned long long pack2(float lo, float hi) {
    unsigned long long r;
    asm("mov.b64 %0, {%1,%2};" : "=l"(r) : "f"(lo), "f"(hi));
    return r;
}
__device__ __forceinline__ void fma2(unsigned long long& d, unsigned long long a, unsigned long long b) {
    asm("fma.rn.f32x2 %0, %1, %2, %0;" : "+l"(d) : "l"(a), "l"(b));
}
__device__ __forceinline__ float2 unpack2(unsigned long long v) {
    float2 f;
    asm("mov.b64 {%0,%1}, %2;" : "=f"(f.x), "=f"(f.y) : "l"(v));
    return f;
}
__device__ __forceinline__ float warpSum(float v) {
    #pragma unroll
    for (int o = 16; o > 0; o >>= 1) v += __shfl_xor_sync(0xffffffffu, v, o);
    return v;
}
__device__ __forceinline__ uint32_t smem_u32(const void* p) {
    uint32_t a;
    asm("{ .reg .u64 t; cvta.to.shared.u64 t, %1; cvt.u32.u64 %0, t; }" : "=r"(a) : "l"(p));
    return a;
}

// ---------------- mma.sync / ldmatrix / cp.async wrappers --------------------
__device__ __forceinline__ void ldmx4(uint32_t* r, uint32_t addr) {
    asm volatile("ldmatrix.sync.aligned.m8n8.x4.shared.b16 {%0,%1,%2,%3}, [%4];"
        : "=r"(r[0]), "=r"(r[1]), "=r"(r[2]), "=r"(r[3]) : "r"(addr));
}
__device__ __forceinline__ void ldmx2(uint32_t* r, uint32_t addr) {
    asm volatile("ldmatrix.sync.aligned.m8n8.x2.shared.b16 {%0,%1}, [%2];"
        : "=r"(r[0]), "=r"(r[1]) : "r"(addr));
}
__device__ __forceinline__ void mma_f16(float* d, const uint32_t* a, const uint32_t* b) {
    asm volatile("mma.sync.aligned.m16n8k16.row.col.f32.f16.f16.f32 "
        "{%0,%1,%2,%3}, {%4,%5,%6,%7}, {%8,%9}, {%0,%1,%2,%3};"
        : "+f"(d[0]), "+f"(d[1]), "+f"(d[2]), "+f"(d[3])
        : "r"(a[0]), "r"(a[1]), "r"(a[2]), "r"(a[3]), "r"(b[0]), "r"(b[1]));
}
__device__ __forceinline__ void cp_async16(uint32_t saddr, const void* gaddr) {
    asm volatile("cp.async.cg.shared.global [%0], [%1], 16;" :: "r"(saddr), "l"(gaddr));
}
__device__ __forceinline__ void cp_commit() {
    asm volatile("cp.async.commit_group;");
}
template <int N>
__device__ __forceinline__ void cp_wait() {
    asm volatile("cp.async.wait_group %0;" :: "n"(N));
}

// ---------------- weight fp16 convert (all 4 in one launch) ------------------
__global__ void conv4_kernel(const float* __restrict__ s0, fp16* __restrict__ d0, int n0,
                             const float* __restrict__ s1, fp16* __restrict__ d1, int n1,
                             const float* __restrict__ s2, fp16* __restrict__ d2, int n2,
                             const float* __restrict__ s3, fp16* __restrict__ d3, int n3) {
    int i = blockIdx.x * 256 + threadIdx.x;
    if (i < n0) { d0[i] = __float2half_rn(s0[i]); return; }
    i -= n0;
    if (i < n1) { d1[i] = __float2half_rn(s1[i]); return; }
    i -= n1;
    if (i < n2) { d2[i] = __float2half_rn(s2[i]); return; }
    i -= n2;
    if (i < n3) { d3[i] = __float2half_rn(s3[i]); }
}

// ---------------- positional-encoding table (computed once per call) ---------
__global__ void pe_kernel(float* __restrict__ PE) {
    const int s = blockIdx.x;         // 0..255
    const int d = threadIdx.x;        // 0..511
    const float c = 0.017988946f;     // log(10000)/512
    const int i2 = d & ~1;
    const float den = expf(-(float)i2 * c);
    const float arg = (float)s * den;
    PE[s * DMODEL + d] = (d & 1) ? cosf(arg) : sinf(arg);
}

// ---------------- embedding (+ PE table, + fp16 round) ----------------
__global__ void embed_kernel(const float* __restrict__ src,
                             const float* __restrict__ ew,
                             const float* __restrict__ eb,
                             const float* __restrict__ PE,
                             float* __restrict__ X,
                             fp16* __restrict__ Xh) {
    __shared__ float sv[VOCAB];
    const int t   = blockIdx.x;
    const int tid = threadIdx.x;              // 128
    if (tid < VOCAB) sv[tid] = src[(size_t)t * VOCAB + tid];
    __syncthreads();
    const int s = t & (SEQ - 1);
    #pragma unroll
    for (int r = 0; r < 4; r++) {
        const int d = tid + r * 128;
        float acc = eb[d] + PE[s * DMODEL + d];
        #pragma unroll
        for (int v = 0; v < VOCAB; v++) acc += sv[v] * ew[d * VOCAB + v];
        const size_t o = (size_t)t * DMODEL + d;
        X[o] = acc;
        Xh[o] = __float2half_rn(acc);
    }
}

// ---------------- HMMA GEMM: C[M,N] = A[M,K] @ W[N,K]^T + bias (fp16 in)
// 128x128x32 CTA tile, 8 warps (2Mx4N, warp tile 64x32), cp.async double buffer.
// OUT=1: (C+bias) -> fp16 Ch.  OUT=2: relu -> fp16 Ch.
template <int OUT>
__global__ __launch_bounds__(256, 2)
void gemm_tc(const fp16* __restrict__ A, const fp16* __restrict__ W,
             const float* __restrict__ bias, fp16* __restrict__ Ch,
             int M, int N, int K) {
    extern __shared__ char smraw[];
    const uint32_t sbase = smem_u32(smraw);
    const int tid  = threadIdx.x;
    const int lane = tid & 31;
    const int wid  = tid >> 5;
    const int wm   = wid >> 2;          // 0..1
    const int wn   = wid & 3;           // 0..3
    const int mBase = blockIdx.y * 128;
    const int nBase = blockIdx.x * 128;

    uint32_t aA[2], aB[2];
    {
        const int rowA = wm * 64 + (lane & 7) + ((lane >> 3) & 1) * 8;
        const int rowB = wn * 32 + (lane & 7);
        #pragma unroll
        for (int ks = 0; ks < 2; ks++) {
            const int cA = (ks * 16 + (lane >> 4) * 8) >> 3;
            const int cB = (ks * 16 + ((lane >> 3) & 1) * 8) >> 3;
            aA[ks] = rowA * 64 + ((cA ^ ((rowA >> 1) & 3)) << 4);
            aB[ks] = rowB * 64 + ((cB ^ ((rowB >> 1) & 3)) << 4);
        }
    }

    float acc[4][4][4];
    #pragma unroll
    for (int i = 0; i < 4; i++)
        #pragma unroll
        for (int j = 0; j < 4; j++)
            #pragma unroll
            for (int k = 0; k < 4; k++) acc[i][j][k] = 0.f;

    const int NC = K >> 5;

    auto load_chunk = [&](uint32_t sbuf, int k0) {
        #pragma unroll
        for (int t = 0; t < 2; t++) {
            const int idx = tid + t * 256;
            const int r = idx >> 2, c = idx & 3;
            const uint32_t so = r * 64 + ((c ^ ((r >> 1) & 3)) << 4);
            const size_t ga = (size_t)(mBase + r) * K + k0 + c * 8;
            const size_t gw = (size_t)(nBase + r) * K + k0 + c * 8;
            cp_async16(sbuf + so,        A + ga);
            cp_async16(sbuf + 8192 + so, W + gw);
        }
    };

    load_chunk(sbase, 0);
    cp_commit();

    for (int kc = 0; kc < NC; kc++) {
        const uint32_t cbuf = sbase + (kc & 1) * 16384;
        if (kc + 1 < NC) {
            load_chunk(sbase + ((kc + 1) & 1) * 16384, (kc + 1) * 32);
            cp_commit();
            cp_wait<1>();
        } else {
            cp_wait<0>();
        }
        __syncthreads();

        #pragma unroll
        for (int ks = 0; ks < 2; ks++) {
            uint32_t Ah[4][4], Bh[4][2];
            #pragma unroll
            for (int mt = 0; mt < 4; mt++)
                ldmx4(Ah[mt], cbuf + aA[ks] + mt * 1024);
            #pragma unroll
            for (int nt = 0; nt < 4; nt++)
                ldmx2(Bh[nt], cbuf + 8192 + aB[ks] + nt * 512);
            #pragma unroll
            for (int mt = 0; mt < 4; mt++)
                #pragma unroll
                for (int nt = 0; nt < 4; nt++)
                    mma_f16(acc[mt][nt], Ah[mt], Bh[nt]);
        }
        __syncthreads();
    }

    const int r0 = mBase + wm * 64 + (lane >> 2);
    const int c0 = nBase + wn * 32 + (lane & 3) * 2;
    #pragma unroll
    for (int mt = 0; mt < 4; mt++) {
        #pragma unroll
        for (int nt = 0; nt < 4; nt++) {
            const int r = r0 + mt * 16;
            const int c = c0 + nt * 8;
            const float b0 = __ldg(bias + c), b1 = __ldg(bias + c + 1);
            float v0 = acc[mt][nt][0] + b0;
            float v1 = acc[mt][nt][1] + b1;
            float v2 = acc[mt][nt][2] + b0;
            float v3 = acc[mt][nt][3] + b1;
            if (OUT == 2) {
                v0 = fmaxf(v0, 0.f); v1 = fmaxf(v1, 0.f);
                v2 = fmaxf(v2, 0.f); v3 = fmaxf(v3, 0.f);
            }
            *(__half2*)(Ch + (size_t)r * N + c)       = __floats2half2_rn(v0, v1);
            *(__half2*)(Ch + (size_t)(r + 8) * N + c) = __floats2half2_rn(v2, v3);
        }
    }
}

// ---------------- FA2-style HMMA attention -----------------------------------
#define ATTN_SMEM ((256 * 72 + 64 * 264) * 2)

__global__ __launch_bounds__(256, 1)
void attn_mma(const fp16* __restrict__ QKVh, fp16* __restrict__ Oh) {
    extern __shared__ fp16 smh[];
    fp16* Ks = smh;               // [256][72]
    fp16* Vt = smh + 256 * 72;    // [64][264]
    const int h = blockIdx.x, b = blockIdx.y;
    const int tid = threadIdx.x, lane = tid & 31, wid = tid >> 5;
    const fp16* base = QKVh + (size_t)b * SEQ * 1536;

    {
        const fp16* src = base + (size_t)tid * 1536 + 512 + h * 64;
        fp16* dst = Ks + tid * 72;
        #pragma unroll
        for (int i = 0; i < 8; i++)
            *(uint4*)(dst + i * 8) = *(const uint4*)(src + i * 8);
    }
    {
        const fp16* src = base + (size_t)tid * 1536 + 1024 + h * 64;
        #pragma unroll
        for (int i = 0; i < 32; i++) {
            const __half2 v = *(const __half2*)(src + 2 * i);
            Vt[(2 * i) * 264 + tid]     = __low2half(v);
            Vt[(2 * i + 1) * 264 + tid] = __high2half(v);
        }
    }
    __syncthreads();

    const uint32_t ksb = smem_u32(Ks);
    const uint32_t vtb = smem_u32(Vt);

    uint32_t qf[2][4][4];
    #pragma unroll
    for (int mt = 0; mt < 2; mt++)
        #pragma unroll
        for (int ks = 0; ks < 4; ks++) {
            const fp16* qp = base + (size_t)(wid * 32 + mt * 16 + (lane >> 2)) * 1536
                             + h * 64 + ks * 16 + (lane & 3) * 2;
            qf[mt][ks][0] = *(const uint32_t*)(qp);
            qf[mt][ks][1] = *(const uint32_t*)(qp + 8 * 1536);
            qf[mt][ks][2] = *(const uint32_t*)(qp + 8);
            qf[mt][ks][3] = *(const uint32_t*)(qp + 8 * 1536 + 8);
        }

    float oacc[2][8][4];
    #pragma unroll
    for (int mt = 0; mt < 2; mt++)
        #pragma unroll
        for (int nt = 0; nt < 8; nt++)
            #pragma unroll
            for (int k = 0; k < 4; k++) oacc[mt][nt][k] = 0.f;
    float m[2][2] = {{-1e30f, -1e30f}, {-1e30f, -1e30f}};
    float l[2][2] = {{0.f, 0.f}, {0.f, 0.f}};

    for (int kc = 0; kc < 16; kc++) {
        float cs[2][2][4];
        #pragma unroll
        for (int mt = 0; mt < 2; mt++)
            #pragma unroll
            for (int nt2 = 0; nt2 < 2; nt2++)
                #pragma unroll
                for (int k = 0; k < 4; k++) cs[mt][nt2][k] = 0.f;

        #pragma unroll
        for (int ks = 0; ks < 4; ks++) {
            uint32_t bk[2][2];
            #pragma unroll
            for (int nt2 = 0; nt2 < 2; nt2++)
                ldmx2(bk[nt2], ksb + ((kc * 16 + nt2 * 8 + (lane & 7)) * 72
                                      + ks * 16 + ((lane >> 3) & 1) * 8) * 2);
            #pragma unroll
            for (int mt = 0; mt < 2; mt++)
                #pragma unroll
                for (int nt2 = 0; nt2 < 2; nt2++)
                    mma_f16(cs[mt][nt2], qf[mt][ks], bk[nt2]);
        }

        uint32_t pf[2][4];
        #pragma unroll
        for (int mt = 0; mt < 2; mt++)
            #pragma unroll
            for (int rh = 0; rh < 2; rh++) {
                const float v0 = cs[mt][0][rh * 2]     * 0.125f;
                const float v1 = cs[mt][0][rh * 2 + 1] * 0.125f;
                const float v2 = cs[mt][1][rh * 2]     * 0.125f;
                const float v3 = cs[mt][1][rh * 2 + 1] * 0.125f;
                float mx = fmaxf(fmaxf(v0, v1), fmaxf(v2, v3));
                mx = fmaxf(mx, __shfl_xor_sync(0xffffffffu, mx, 1));
                mx = fmaxf(mx, __shfl_xor_sync(0xffffffffu, mx, 2));
                const float mnew = fmaxf(m[mt][rh], mx);
                const float corr = __expf(m[mt][rh] - mnew);
                m[mt][rh] = mnew;
                const float p0 = __expf(v0 - mnew);
                const float p1 = __expf(v1 - mnew);
                const float p2 = __expf(v2 - mnew);
                const float p3 = __expf(v3 - mnew);
                float ls = (p0 + p1) + (p2 + p3);
                ls += __shfl_xor_sync(0xffffffffu, ls, 1);
                ls += __shfl_xor_sync(0xffffffffu, ls, 2);
                l[mt][rh] = l[mt][rh] * corr + ls;
                #pragma unroll
                for (int nt = 0; nt < 8; nt++) {
                    oacc[mt][nt][rh * 2]     *= corr;
                    oacc[mt][nt][rh * 2 + 1] *= corr;
                }
                const __half2 ph0 = __floats2half2_rn(p0, p1);
                const __half2 ph1 = __floats2half2_rn(p2, p3);
                pf[mt][rh]     = *(const uint32_t*)&ph0;
                pf[mt][rh + 2] = *(const uint32_t*)&ph1;
            }

        #pragma unroll
        for (int nt = 0; nt < 8; nt++) {
            uint32_t bv[2];
            ldmx2(bv, vtb + ((nt * 8 + (lane & 7)) * 264
                             + kc * 16 + ((lane >> 3) & 1) * 8) * 2);
            mma_f16(oacc[0][nt], pf[0], bv);
            mma_f16(oacc[1][nt], pf[1], bv);
        }
    }

    #pragma unroll
    for (int mt = 0; mt < 2; mt++) {
        const float i0 = 1.f / l[mt][0];
        const float i1 = 1.f / l[mt][1];
        const int r = b * SEQ + wid * 32 + mt * 16 + (lane >> 2);
        #pragma unroll
        for (int nt = 0; nt < 8; nt++) {
            const int c = h * 64 + nt * 8 + (lane & 3) * 2;
            *(__half2*)(Oh + (size_t)r * DMODEL + c) =
                __floats2half2_rn(oacc[mt][nt][0] * i0, oacc[mt][nt][1] * i0);
            *(__half2*)(Oh + (size_t)(r + 8) * DMODEL + c) =
                __floats2half2_rn(oacc[mt][nt][2] * i1, oacc[mt][nt][3] * i1);
        }
    }
}

// ---------------- residual add + LayerNorm (fp16 residual input) -------------
__global__ void add_ln_kernel(float* __restrict__ X, const fp16* __restrict__ R,
                              const float* __restrict__ gamma, const float* __restrict__ beta,
                              fp16* __restrict__ Xh) {
    const int t = blockIdx.x;
    const int tid = threadIdx.x;    // 256
    const size_t o = (size_t)t * DMODEL;
    const float y0 = X[o + tid]       + __half2float(R[o + tid]);
    const float y1 = X[o + tid + 256] + __half2float(R[o + tid + 256]);
    float s  = y0 + y1;
    float sq = y0 * y0 + y1 * y1;

    __shared__ float sS[8], sQ[8];
    const float ws = warpSum(s), wq = warpSum(sq);
    const int w = tid >> 5, ln = tid & 31;
    if (ln == 0) { sS[w] = ws; sQ[w] = wq; }
    __syncthreads();
    float tS = 0.f, tQ = 0.f;
    #pragma unroll
    for (int i = 0; i < 8; i++) { tS += sS[i]; tQ += sQ[i]; }
    const float mean = tS * (1.f / DMODEL);
    const float var  = tQ * (1.f / DMODEL) - mean * mean;
    const float inv  = rsqrtf(var + 1e-5f);
    const float z0 = (y0 - mean) * inv * gamma[tid]       + beta[tid];
    const float z1 = (y1 - mean) * inv * gamma[tid + 256] + beta[tid + 256];
    X[o + tid]       = z0;
    X[o + tid + 256] = z1;
    Xh[o + tid]       = __float2half_rn(z0);
    Xh[o + tid + 256] = __float2half_rn(z1);
}

// ---------------- latent GEMM split-K (fp32, f32x2) --------------------------
__global__ __launch_bounds__(256, 2)
void latent_partial(const float* __restrict__ Xf, const float* __restrict__ Wl,
                    float* __restrict__ P) {
    __shared__ float As[16][64];
    __shared__ float Ws[16][64];
    const int tid = threadIdx.x;
    const int tx = tid & 15, ty = tid >> 4;
    const int nBase = blockIdx.x * 64;
    const int kBase = blockIdx.y * 2048;
    const int lr = tid >> 2;
    const int lk = (tid & 3) * 4;

    unsigned long long acc[4][2];
    #pragma unroll
    for (int i = 0; i < 4; i++) { acc[i][0] = 0ULL; acc[i][1] = 0ULL; }

    const float* Ab = Xf + (size_t)lr * SD + kBase;
    const float* Wb = Wl + (size_t)(nBase + lr) * SD + kBase;

    for (int k0 = 0; k0 < 2048; k0 += 16) {
        float4 a = *(const float4*)(Ab + k0 + lk);
        float4 w = *(const float4*)(Wb + k0 + lk);
        __syncthreads();
        As[lk + 0][lr] = a.x; As[lk + 1][lr] = a.y; As[lk + 2][lr] = a.z; As[lk + 3][lr] = a.w;
        Ws[lk + 0][lr] = w.x; Ws[lk + 1][lr] = w.y; Ws[lk + 2][lr] = w.z; Ws[lk + 3][lr] = w.w;
        __syncthreads();
        #pragma unroll
        for (int kk = 0; kk < 16; kk++) {
            float a4[4];
            #pragma unroll
            for (int i = 0; i < 4; i++) a4[i] = As[kk][ty * 4 + i];
            const unsigned long long* wrow = (const unsigned long long*)&Ws[kk][0];
            unsigned long long w2[2] = { wrow[tx * 2], wrow[tx * 2 + 1] };
            #pragma unroll
            for (int i = 0; i < 4; i++) {
                unsigned long long ad = pack2(a4[i], a4[i]);
                fma2(acc[i][0], ad, w2[0]);
                fma2(acc[i][1], ad, w2[1]);
            }
        }
    }
    #pragma unroll
    for (int i = 0; i < 4; i++) {
        const int bb = ty * 4 + i;
        #pragma unroll
        for (int j = 0; j < 2; j++) {
            float2 v = unpack2(acc[i][j]);
            const int n = nBase + tx * 4 + 2 * j;
            P[(size_t)blockIdx.y * (BATCH * DLAT) + bb * DLAT + n]     = v.x;
            P[(size_t)blockIdx.y * (BATCH * DLAT) + bb * DLAT + n + 1] = v.y;
        }
    }
}

__global__ void latent_reduce(const float* __restrict__ P, const float* __restrict__ lb,
                              float* __restrict__ mem) {
    const int idx = blockIdx.x * 256 + threadIdx.x;  // 16384
    float s = lb[idx & (DLAT - 1)];
    #pragma unroll 8
    for (int ks = 0; ks < 64; ks++) s += P[(size_t)ks * (BATCH * DLAT) + idx];
    mem[idx] = s;
}

__global__ void head_kernel(const float* __restrict__ mem, const float* __restrict__ hw,
                            const float* __restrict__ hb, float* __restrict__ out) {
    const int b = blockIdx.x;
    const int tid = threadIdx.x;  // 256
    float v = mem[b * DLAT + tid] * hw[tid];
    __shared__ float sS[8];
    const float ws = warpSum(v);
    if ((tid & 31) == 0) sS[tid >> 5] = ws;
    __syncthreads();
    if (tid == 0) {
        float t = 0.f;
        #pragma unroll
        for (int i = 0; i < 8; i++) t += sS[i];
        const float z = t + hb[0];
        out[b] = 1.f / (1.f + expf(-z));
    }
}

// ---------------- launch ----------------
#define GEMM_SMEM (2 * 16384)

extern "C" void kernel_launch(void* const* d_in, const int* in_sizes, int n_in,
                              void* d_out, int out_size) {
    const float* src    = (const float*)d_in[0];
    const float* emb_w  = (const float*)d_in[1];
    const float* emb_b  = (const float*)d_in[2];
    const float* qkv_w  = (const float*)d_in[3];
    const float* qkv_b  = (const float*)d_in[4];
    const float* out_w  = (const float*)d_in[5];
    const float* out_b  = (const float*)d_in[6];
    const float* ff1_w  = (const float*)d_in[7];
    const float* ff1_b  = (const float*)d_in[8];
    const float* ff2_w  = (const float*)d_in[9];
    const float* ff2_b  = (const float*)d_in[10];
    const float* ln1_g  = (const float*)d_in[11];
    const float* ln1_b  = (const float*)d_in[12];
    const float* ln2_g  = (const float*)d_in[13];
    const float* ln2_b  = (const float*)d_in[14];
    const float* lat_w  = (const float*)d_in[15];
    const float* lat_b  = (const float*)d_in[16];
    const float* head_w = (const float*)d_in[17];
    const float* head_b = (const float*)d_in[18];
    float* out = (float*)d_out;

    float *X, *PE, *P, *MEM;
    fp16 *QKVh, *Xh, *Oh, *Th, *Hh, *Wq, *Wo, *W1, *W2;
    cudaGetSymbolAddress((void**)&X,    g_X);
    cudaGetSymbolAddress((void**)&PE,   g_PE);
    cudaGetSymbolAddress((void**)&P,    g_LP);
    cudaGetSymbolAddress((void**)&MEM,  g_MEM);
    cudaGetSymbolAddress((void**)&QKVh, g_QKVh);
    cudaGetSymbolAddress((void**)&Xh,   g_Xh);
    cudaGetSymbolAddress((void**)&Oh,   g_Oh);
    cudaGetSymbolAddress((void**)&Th,   g_Th);
    cudaGetSymbolAddress((void**)&Hh,   g_Hh);
    cudaGetSymbolAddress((void**)&Wq,   g_Wq);
    cudaGetSymbolAddress((void**)&Wo,   g_Wo);
    cudaGetSymbolAddress((void**)&W1,   g_W1);
    cudaGetSymbolAddress((void**)&W2,   g_W2);

    cudaFuncSetAttribute(attn_mma,
                         cudaFuncAttributeMaxDynamicSharedMemorySize, ATTN_SMEM);
    cudaFuncSetAttribute(gemm_tc<1>,
                         cudaFuncAttributeMaxDynamicSharedMemorySize, GEMM_SMEM);
    cudaFuncSetAttribute(gemm_tc<2>,
                         cudaFuncAttributeMaxDynamicSharedMemorySize, GEMM_SMEM);

    // one-time-per-call weight converts (fp32 -> fp16), single launch
    {
        const int nq = NLAYER * 3 * DMODEL * DMODEL;
        const int no = NLAYER * DMODEL * DMODEL;
        const int n1 = NLAYER * DFF * DMODEL;
        const int n2 = NLAYER * DMODEL * DFF;
        const int ntot = nq + no + n1 + n2;
        conv4_kernel<<<(ntot + 255) / 256, 256>>>(qkv_w, Wq, nq, out_w, Wo, no,
                                                  ff1_w, W1, n1, ff2_w, W2, n2);
    }

    pe_kernel<<<SEQ, DMODEL>>>(PE);
    embed_kernel<<<NTOK, 128>>>(src, emb_w, emb_b, PE, X, Xh);

    for (int l = 0; l < NLAYER; l++) {
        gemm_tc<1><<<dim3(12, 128), 256, GEMM_SMEM>>>(
            Xh, Wq + (size_t)l * 1536 * DMODEL,
            qkv_b + l * 1536, QKVh, NTOK, 1536, DMODEL);
        attn_mma<<<dim3(NHEAD, BATCH), 256, ATTN_SMEM>>>(QKVh, Oh);
        gemm_tc<1><<<dim3(4, 128), 256, GEMM_SMEM>>>(
            Oh, Wo + (size_t)l * DMODEL * DMODEL,
            out_b + l * DMODEL, Th, NTOK, DMODEL, DMODEL);
        add_ln_kernel<<<NTOK, 256>>>(X, Th, ln1_g + l * DMODEL, ln1_b + l * DMODEL, Xh);
        gemm_tc<2><<<dim3(16, 128), 256, GEMM_SMEM>>>(
            Xh, W1 + (size_t)l * DFF * DMODEL,
            ff1_b + l * DFF, Hh, NTOK, DFF, DMODEL);
        gemm_tc<1><<<dim3(4, 128), 256, GEMM_SMEM>>>(
            Hh, W2 + (size_t)l * DMODEL * DFF,
            ff2_b + l * DMODEL, Th, NTOK, DMODEL, DFF);
        add_ln_kernel<<<NTOK, 256>>>(X, Th, ln2_g + l * DMODEL, ln2_b + l * DMODEL, Xh);
    }

    latent_partial<<<dim3(4, 64), 256>>>(X, lat_w, P);
    latent_reduce<<<64, 256>>>(P, lat_b, MEM);
    head_kernel<<<BATCH, 256>>>(MEM, head_w, head_b, out);
}

// round 16
// speedup vs baseline: 1.2014x; 1.0611x over previous
#include <cuda_runtime.h>
#include <cuda_fp16.h>
#include <math.h>
#include <stdint.h>

// Problem constants
#define BATCH   64
#define SEQ     256
#define NTOK    16384      // BATCH*SEQ
#define VOCAB   16
#define DMODEL  512
#define DFF     2048
#define NLAYER  6
#define NHEAD   8
#define DHEAD   64
#define DLAT    256
#define SD      131072     // SEQ*DMODEL

typedef __half fp16;

// ---------------- scratch (static __device__ — allocation-free) ----------------
__device__ float g_X    [NTOK * DMODEL];
__device__ float g_PE   [SEQ * DMODEL];
__device__ fp16  g_QKVh [NTOK * 3 * DMODEL];
__device__ fp16  g_Xh   [NTOK * DMODEL];
__device__ fp16  g_Oh   [NTOK * DMODEL];
__device__ fp16  g_Th   [NTOK * DMODEL];
__device__ fp16  g_Hh   [NTOK * DFF];
__device__ fp16  g_Wq   [NLAYER * 3 * DMODEL * DMODEL];
__device__ fp16  g_Wo   [NLAYER * DMODEL * DMODEL];
__device__ fp16  g_W1   [NLAYER * DFF * DMODEL];
__device__ fp16  g_W2   [NLAYER * DMODEL * DFF];
__device__ float g_LP   [64 * BATCH * DLAT];
__device__ float g_MEM  [BATCH * DLAT];

// ---------------- helpers ----------------
__device__ __forceinline__ unsigned long long pack2(float lo, float hi) {
    unsigned long long r;
    asm("mov.b64 %0, {%1,%2};" : "=l"(r) : "f"(lo), "f"(hi));
    return r;
}
__device__ __forceinline__ void fma2(unsigned long long& d, unsigned long long a, unsigned long long b) {
    asm("fma.rn.f32x2 %0, %1, %2, %0;" : "+l"(d) : "l"(a), "l"(b));
}
__device__ __forceinline__ float2 unpack2(unsigned long long v) {
    float2 f;
    asm("mov.b64 {%0,%1}, %2;" : "=f"(f.x), "=f"(f.y) : "l"(v));
    return f;
}
__device__ __forceinline__ float warpSum(float v) {
    #pragma unroll
    for (int o = 16; o > 0; o >>= 1) v += __shfl_xor_sync(0xffffffffu, v, o);
    return v;
}
__device__ __forceinline__ uint32_t smem_u32(const void* p) {
    uint32_t a;
    asm("{ .reg .u64 t; cvta.to.shared.u64 t, %1; cvt.u32.u64 %0, t; }" : "=r"(a) : "l"(p));
    return a;
}

// ---------------- mma.sync / ldmatrix / cp.async wrappers --------------------
__device__ __forceinline__ void ldmx4(uint32_t* r, uint32_t addr) {
    asm volatile("ldmatrix.sync.aligned.m8n8.x4.shared.b16 {%0,%1,%2,%3}, [%4];"
        : "=r"(r[0]), "=r"(r[1]), "=r"(r[2]), "=r"(r[3]) : "r"(addr));
}
__device__ __forceinline__ void ldmx2(uint32_t* r, uint32_t addr) {
    asm volatile("ldmatrix.sync.aligned.m8n8.x2.shared.b16 {%0,%1}, [%2];"
        : "=r"(r[0]), "=r"(r[1]) : "r"(addr));
}
__device__ __forceinline__ void mma_f16(float* d, const uint32_t* a, const uint32_t* b) {
    asm volatile("mma.sync.aligned.m16n8k16.row.col.f32.f16.f16.f32 "
        "{%0,%1,%2,%3}, {%4,%5,%6,%7}, {%8,%9}, {%0,%1,%2,%3};"
        : "+f"(d[0]), "+f"(d[1]), "+f"(d[2]), "+f"(d[3])
        : "r"(a[0]), "r"(a[1]), "r"(a[2]), "r"(a[3]), "r"(b[0]), "r"(b[1]));
}
__device__ __forceinline__ void cp_async16(uint32_t saddr, const void* gaddr) {
    asm volatile("cp.async.cg.shared.global [%0], [%1], 16;" :: "r"(saddr), "l"(gaddr));
}
__device__ __forceinline__ void cp_commit() {
    asm volatile("cp.async.commit_group;");
}
template <int N>
__device__ __forceinline__ void cp_wait() {
    asm volatile("cp.async.wait_group %0;" :: "n"(N));
}

// ---------------- weight fp16 convert (all 4 in one launch) ------------------
__global__ void conv4_kernel(const float* __restrict__ s0, fp16* __restrict__ d0, int n0,
                             const float* __restrict__ s1, fp16* __restrict__ d1, int n1,
                             const float* __restrict__ s2, fp16* __restrict__ d2, int n2,
                             const float* __restrict__ s3, fp16* __restrict__ d3, int n3) {
    int i = blockIdx.x * 256 + threadIdx.x;
    if (i < n0) { d0[i] = __float2half_rn(s0[i]); return; }
    i -= n0;
    if (i < n1) { d1[i] = __float2half_rn(s1[i]); return; }
    i -= n1;
    if (i < n2) { d2[i] = __float2half_rn(s2[i]); return; }
    i -= n2;
    if (i < n3) { d3[i] = __float2half_rn(s3[i]); }
}

// ---------------- positional-encoding table (computed once per call) ---------
__global__ void pe_kernel(float* __restrict__ PE) {
    const int s = blockIdx.x;         // 0..255
    const int d = threadIdx.x;        // 0..511
    const float c = 0.017988946f;     // log(10000)/512
    const int i2 = d & ~1;
    const float den = expf(-(float)i2 * c);
    const float arg = (float)s * den;
    PE[s * DMODEL + d] = (d & 1) ? cosf(arg) : sinf(arg);
}

// ---------------- embedding (+ PE table, + fp16 round) ----------------
__global__ void embed_kernel(const float* __restrict__ src,
                             const float* __restrict__ ew,
                             const float* __restrict__ eb,
                             const float* __restrict__ PE,
                             float* __restrict__ X,
                             fp16* __restrict__ Xh) {
    __shared__ float sv[VOCAB];
    const int t   = blockIdx.x;
    const int tid = threadIdx.x;              // 128
    if (tid < VOCAB) sv[tid] = src[(size_t)t * VOCAB + tid];
    __syncthreads();
    const int s = t & (SEQ - 1);
    #pragma unroll
    for (int r = 0; r < 4; r++) {
        const int d = tid + r * 128;
        float acc = eb[d] + PE[s * DMODEL + d];
        #pragma unroll
        for (int v = 0; v < VOCAB; v++) acc += sv[v] * ew[d * VOCAB + v];
        const size_t o = (size_t)t * DMODEL + d;
        X[o] = acc;
        Xh[o] = __float2half_rn(acc);
    }
}

// ---------------- HMMA GEMM: C[M,N] = A[M,K] @ W[N,K]^T + bias (fp16 in)
// 128x128x32 CTA tile, 8 warps (2Mx4N, warp tile 64x32).
// 3-stage cp.async pipeline (loads 2 chunks ahead), ONE barrier per chunk,
// B fragments via paired ldmx4 (2 n-tiles per op).
// OUT=1: (C+bias) -> fp16 Ch.  OUT=2: relu -> fp16 Ch.
template <int OUT>
__global__ __launch_bounds__(256, 2)
void gemm_tc(const fp16* __restrict__ A, const fp16* __restrict__ W,
             const float* __restrict__ bias, fp16* __restrict__ Ch,
             int M, int N, int K) {
    extern __shared__ char smraw[];
    const uint32_t sbase = smem_u32(smraw);
    const int tid  = threadIdx.x;
    const int lane = tid & 31;
    const int wid  = tid >> 5;
    const int wm   = wid >> 2;          // 0..1
    const int wn   = wid & 3;           // 0..3
    const int mBase = blockIdx.y * 128;
    const int nBase = blockIdx.x * 128;

    uint32_t aA[2], aB[2];
    {
        const int rowA = wm * 64 + (lane & 7) + ((lane >> 3) & 1) * 8;
        // paired-B ldmx4: lanes 0-7 -> (tile n0, k0), 8-15 -> (n0, k8),
        //                 16-23 -> (tile n0+1, k0), 24-31 -> (n0+1, k8)
        const int rowB = wn * 32 + (lane >> 4) * 8 + (lane & 7);
        #pragma unroll
        for (int ks = 0; ks < 2; ks++) {
            const int cA = (ks * 16 + (lane >> 4) * 8) >> 3;
            const int cB = (ks * 16 + ((lane >> 3) & 1) * 8) >> 3;
            aA[ks] = rowA * 64 + ((cA ^ ((rowA >> 1) & 3)) << 4);
            aB[ks] = rowB * 64 + ((cB ^ ((rowB >> 1) & 3)) << 4);
        }
    }

    float acc[4][4][4];
    #pragma unroll
    for (int i = 0; i < 4; i++)
        #pragma unroll
        for (int j = 0; j < 4; j++)
            #pragma unroll
            for (int k = 0; k < 4; k++) acc[i][j][k] = 0.f;

    const int NC = K >> 5;

    auto load_chunk = [&](uint32_t sbuf, int k0) {
        #pragma unroll
        for (int t = 0; t < 2; t++) {
            const int idx = tid + t * 256;
            const int r = idx >> 2, c = idx & 3;
            const uint32_t so = r * 64 + ((c ^ ((r >> 1) & 3)) << 4);
            const size_t ga = (size_t)(mBase + r) * K + k0 + c * 8;
            const size_t gw = (size_t)(nBase + r) * K + k0 + c * 8;
            cp_async16(sbuf + so,        A + ga);
            cp_async16(sbuf + 8192 + so, W + gw);
        }
    };

    load_chunk(sbase, 0);
    cp_commit();
    if (NC > 1) { load_chunk(sbase + 16384, 32); cp_commit(); }

    for (int kc = 0; kc < NC; kc++) {
        if (kc + 1 < NC) cp_wait<1>(); else cp_wait<0>();
        __syncthreads();
        if (kc + 2 < NC) {
            load_chunk(sbase + ((kc + 2) % 3) * 16384, (kc + 2) * 32);
            cp_commit();
        }
        const uint32_t cbuf = sbase + (kc % 3) * 16384;

        #pragma unroll
        for (int ks = 0; ks < 2; ks++) {
            uint32_t Ah[4][4], Bp[2][4];
            #pragma unroll
            for (int mt = 0; mt < 4; mt++)
                ldmx4(Ah[mt], cbuf + aA[ks] + mt * 1024);
            #pragma unroll
            for (int pr = 0; pr < 2; pr++)
                ldmx4(Bp[pr], cbuf + 8192 + aB[ks] + pr * 1024);
            #pragma unroll
            for (int mt = 0; mt < 4; mt++)
                #pragma unroll
                for (int nt = 0; nt < 4; nt++)
                    mma_f16(acc[mt][nt], Ah[mt], &Bp[nt >> 1][(nt & 1) * 2]);
        }
        // NOTE: no trailing barrier — top-of-loop barrier covers buffer reuse
    }

    const int r0 = mBase + wm * 64 + (lane >> 2);
    const int c0 = nBase + wn * 32 + (lane & 3) * 2;
    #pragma unroll
    for (int mt = 0; mt < 4; mt++) {
        #pragma unroll
        for (int nt = 0; nt < 4; nt++) {
            const int r = r0 + mt * 16;
            const int c = c0 + nt * 8;
            const float b0 = __ldg(bias + c), b1 = __ldg(bias + c + 1);
            float v0 = acc[mt][nt][0] + b0;
            float v1 = acc[mt][nt][1] + b1;
            float v2 = acc[mt][nt][2] + b0;
            float v3 = acc[mt][nt][3] + b1;
            if (OUT == 2) {
                v0 = fmaxf(v0, 0.f); v1 = fmaxf(v1, 0.f);
                v2 = fmaxf(v2, 0.f); v3 = fmaxf(v3, 0.f);
            }
            *(__half2*)(Ch + (size_t)r * N + c)       = __floats2half2_rn(v0, v1);
            *(__half2*)(Ch + (size_t)(r + 8) * N + c) = __floats2half2_rn(v2, v3);
        }
    }
}

// ---------------- FA2-style HMMA attention -----------------------------------
#define ATTN_SMEM ((256 * 72 + 64 * 264) * 2)

__global__ __launch_bounds__(256, 1)
void attn_mma(const fp16* __restrict__ QKVh, fp16* __restrict__ Oh) {
    extern __shared__ fp16 smh[];
    fp16* Ks = smh;               // [256][72]
    fp16* Vt = smh + 256 * 72;    // [64][264]
    const int h = blockIdx.x, b = blockIdx.y;
    const int tid = threadIdx.x, lane = tid & 31, wid = tid >> 5;
    const fp16* base = QKVh + (size_t)b * SEQ * 1536;

    {
        const fp16* src = base + (size_t)tid * 1536 + 512 + h * 64;
        fp16* dst = Ks + tid * 72;
        #pragma unroll
        for (int i = 0; i < 8; i++)
            *(uint4*)(dst + i * 8) = *(const uint4*)(src + i * 8);
    }
    {
        const fp16* src = base + (size_t)tid * 1536 + 1024 + h * 64;
        #pragma unroll
        for (int i = 0; i < 32; i++) {
            const __half2 v = *(const __half2*)(src + 2 * i);
            Vt[(2 * i) * 264 + tid]     = __low2half(v);
            Vt[(2 * i + 1) * 264 + tid] = __high2half(v);
        }
    }
    __syncthreads();

    const uint32_t ksb = smem_u32(Ks);
    const uint32_t vtb = smem_u32(Vt);

    uint32_t qf[2][4][4];
    #pragma unroll
    for (int mt = 0; mt < 2; mt++)
        #pragma unroll
        for (int ks = 0; ks < 4; ks++) {
            const fp16* qp = base + (size_t)(wid * 32 + mt * 16 + (lane >> 2)) * 1536
                             + h * 64 + ks * 16 + (lane & 3) * 2;
            qf[mt][ks][0] = *(const uint32_t*)(qp);
            qf[mt][ks][1] = *(const uint32_t*)(qp + 8 * 1536);
            qf[mt][ks][2] = *(const uint32_t*)(qp + 8);
            qf[mt][ks][3] = *(const uint32_t*)(qp + 8 * 1536 + 8);
        }

    float oacc[2][8][4];
    #pragma unroll
    for (int mt = 0; mt < 2; mt++)
        #pragma unroll
        for (int nt = 0; nt < 8; nt++)
            #pragma unroll
            for (int k = 0; k < 4; k++) oacc[mt][nt][k] = 0.f;
    float m[2][2] = {{-1e30f, -1e30f}, {-1e30f, -1e30f}};
    float l[2][2] = {{0.f, 0.f}, {0.f, 0.f}};

    for (int kc = 0; kc < 16; kc++) {
        float cs[2][2][4];
        #pragma unroll
        for (int mt = 0; mt < 2; mt++)
            #pragma unroll
            for (int nt2 = 0; nt2 < 2; nt2++)
                #pragma unroll
                for (int k = 0; k < 4; k++) cs[mt][nt2][k] = 0.f;

        #pragma unroll
        for (int ks = 0; ks < 4; ks++) {
            uint32_t bk[2][2];
            #pragma unroll
            for (int nt2 = 0; nt2 < 2; nt2++)
                ldmx2(bk[nt2], ksb + ((kc * 16 + nt2 * 8 + (lane & 7)) * 72
                                      + ks * 16 + ((lane >> 3) & 1) * 8) * 2);
            #pragma unroll
            for (int mt = 0; mt < 2; mt++)
                #pragma unroll
                for (int nt2 = 0; nt2 < 2; nt2++)
                    mma_f16(cs[mt][nt2], qf[mt][ks], bk[nt2]);
        }

        uint32_t pf[2][4];
        #pragma unroll
        for (int mt = 0; mt < 2; mt++)
            #pragma unroll
            for (int rh = 0; rh < 2; rh++) {
                const float v0 = cs[mt][0][rh * 2]     * 0.125f;
                const float v1 = cs[mt][0][rh * 2 + 1] * 0.125f;
                const float v2 = cs[mt][1][rh * 2]     * 0.125f;
                const float v3 = cs[mt][1][rh * 2 + 1] * 0.125f;
                float mx = fmaxf(fmaxf(v0, v1), fmaxf(v2, v3));
                mx = fmaxf(mx, __shfl_xor_sync(0xffffffffu, mx, 1));
                mx = fmaxf(mx, __shfl_xor_sync(0xffffffffu, mx, 2));
                const float mnew = fmaxf(m[mt][rh], mx);
                const float corr = __expf(m[mt][rh] - mnew);
                m[mt][rh] = mnew;
                const float p0 = __expf(v0 - mnew);
                const float p1 = __expf(v1 - mnew);
                const float p2 = __expf(v2 - mnew);
                const float p3 = __expf(v3 - mnew);
                float ls = (p0 + p1) + (p2 + p3);
                ls += __shfl_xor_sync(0xffffffffu, ls, 1);
                ls += __shfl_xor_sync(0xffffffffu, ls, 2);
                l[mt][rh] = l[mt][rh] * corr + ls;
                #pragma unroll
                for (int nt = 0; nt < 8; nt++) {
                    oacc[mt][nt][rh * 2]     *= corr;
                    oacc[mt][nt][rh * 2 + 1] *= corr;
                }
                const __half2 ph0 = __floats2half2_rn(p0, p1);
                const __half2 ph1 = __floats2half2_rn(p2, p3);
                pf[mt][rh]     = *(const uint32_t*)&ph0;
                pf[mt][rh + 2] = *(const uint32_t*)&ph1;
            }

        #pragma unroll
        for (int nt = 0; nt < 8; nt++) {
            uint32_t bv[2];
            ldmx2(bv, vtb + ((nt * 8 + (lane & 7)) * 264
                             + kc * 16 + ((lane >> 3) & 1) * 8) * 2);
            mma_f16(oacc[0][nt], pf[0], bv);
            mma_f16(oacc[1][nt], pf[1], bv);
        }
    }

    #pragma unroll
    for (int mt = 0; mt < 2; mt++) {
        const float i0 = 1.f / l[mt][0];
        const float i1 = 1.f / l[mt][1];
        const int r = b * SEQ + wid * 32 + mt * 16 + (lane >> 2);
        #pragma unroll
        for (int nt = 0; nt < 8; nt++) {
            const int c = h * 64 + nt * 8 + (lane & 3) * 2;
            *(__half2*)(Oh + (size_t)r * DMODEL + c) =
                __floats2half2_rn(oacc[mt][nt][0] * i0, oacc[mt][nt][1] * i0);
            *(__half2*)(Oh + (size_t)(r + 8) * DMODEL + c) =
                __floats2half2_rn(oacc[mt][nt][2] * i1, oacc[mt][nt][3] * i1);
        }
    }
}

// ---------------- residual add + LayerNorm (fp16 residual input) -------------
__global__ void add_ln_kernel(float* __restrict__ X, const fp16* __restrict__ R,
                              const float* __restrict__ gamma, const float* __restrict__ beta,
                              fp16* __restrict__ Xh) {
    const int t = blockIdx.x;
    const int tid = threadIdx.x;    // 256
    const size_t o = (size_t)t * DMODEL;
    const float y0 = X[o + tid]       + __half2float(R[o + tid]);
    const float y1 = X[o + tid + 256] + __half2float(R[o + tid + 256]);
    float s  = y0 + y1;
    float sq = y0 * y0 + y1 * y1;

    __shared__ float sS[8], sQ[8];
    const float ws = warpSum(s), wq = warpSum(sq);
    const int w = tid >> 5, ln = tid & 31;
    if (ln == 0) { sS[w] = ws; sQ[w] = wq; }
    __syncthreads();
    float tS = 0.f, tQ = 0.f;
    #pragma unroll
    for (int i = 0; i < 8; i++) { tS += sS[i]; tQ += sQ[i]; }
    const float mean = tS * (1.f / DMODEL);
    const float var  = tQ * (1.f / DMODEL) - mean * mean;
    const float inv  = rsqrtf(var + 1e-5f);
    const float z0 = (y0 - mean) * inv * gamma[tid]       + beta[tid];
    const float z1 = (y1 - mean) * inv * gamma[tid + 256] + beta[tid + 256];
    X[o + tid]       = z0;
    X[o + tid + 256] = z1;
    Xh[o + tid]       = __float2half_rn(z0);
    Xh[o + tid + 256] = __float2half_rn(z1);
}

// ---------------- latent GEMM split-K (fp32, f32x2) --------------------------
__global__ __launch_bounds__(256, 2)
void latent_partial(const float* __restrict__ Xf, const float* __restrict__ Wl,
                    float* __restrict__ P) {
    __shared__ float As[16][64];
    __shared__ float Ws[16][64];
    const int tid = threadIdx.x;
    const int tx = tid & 15, ty = tid >> 4;
    const int nBase = blockIdx.x * 64;
    const int kBase = blockIdx.y * 2048;
    const int lr = tid >> 2;
    const int lk = (tid & 3) * 4;

    unsigned long long acc[4][2];
    #pragma unroll
    for (int i = 0; i < 4; i++) { acc[i][0] = 0ULL; acc[i][1] = 0ULL; }

    const float* Ab = Xf + (size_t)lr * SD + kBase;
    const float* Wb = Wl + (size_t)(nBase + lr) * SD + kBase;

    for (int k0 = 0; k0 < 2048; k0 += 16) {
        float4 a = *(const float4*)(Ab + k0 + lk);
        float4 w = *(const float4*)(Wb + k0 + lk);
        __syncthreads();
        As[lk + 0][lr] = a.x; As[lk + 1][lr] = a.y; As[lk + 2][lr] = a.z; As[lk + 3][lr] = a.w;
        Ws[lk + 0][lr] = w.x; Ws[lk + 1][lr] = w.y; Ws[lk + 2][lr] = w.z; Ws[lk + 3][lr] = w.w;
        __syncthreads();
        #pragma unroll
        for (int kk = 0; kk < 16; kk++) {
            float a4[4];
            #pragma unroll
            for (int i = 0; i < 4; i++) a4[i] = As[kk][ty * 4 + i];
            const unsigned long long* wrow = (const unsigned long long*)&Ws[kk][0];
            unsigned long long w2[2] = { wrow[tx * 2], wrow[tx * 2 + 1] };
            #pragma unroll
            for (int i = 0; i < 4; i++) {
                unsigned long long ad = pack2(a4[i], a4[i]);
                fma2(acc[i][0], ad, w2[0]);
                fma2(acc[i][1], ad, w2[1]);
            }
        }
    }
    #pragma unroll
    for (int i = 0; i < 4; i++) {
        const int bb = ty * 4 + i;
        #pragma unroll
        for (int j = 0; j < 2; j++) {
            float2 v = unpack2(acc[i][j]);
            const int n = nBase + tx * 4 + 2 * j;
            P[(size_t)blockIdx.y * (BATCH * DLAT) + bb * DLAT + n]     = v.x;
            P[(size_t)blockIdx.y * (BATCH * DLAT) + bb * DLAT + n + 1] = v.y;
        }
    }
}

__global__ void latent_reduce(const float* __restrict__ P, const float* __restrict__ lb,
                              float* __restrict__ mem) {
    const int idx = blockIdx.x * 256 + threadIdx.x;  // 16384
    float s = lb[idx & (DLAT - 1)];
    #pragma unroll 8
    for (int ks = 0; ks < 64; ks++) s += P[(size_t)ks * (BATCH * DLAT) + idx];
    mem[idx] = s;
}

__global__ void head_kernel(const float* __restrict__ mem, const float* __restrict__ hw,
                            const float* __restrict__ hb, float* __restrict__ out) {
    const int b = blockIdx.x;
    const int tid = threadIdx.x;  // 256
    float v = mem[b * DLAT + tid] * hw[tid];
    __shared__ float sS[8];
    const float ws = warpSum(v);
    if ((tid & 31) == 0) sS[tid >> 5] = ws;
    __syncthreads();
    if (tid == 0) {
        float t = 0.f;
        #pragma unroll
        for (int i = 0; i < 8; i++) t += sS[i];
        const float z = t + hb[0];
        out[b] = 1.f / (1.f + expf(-z));
    }
}

// ---------------- launch ----------------
#define GEMM_SMEM (3 * 16384)

extern "C" void kernel_launch(void* const* d_in, const int* in_sizes, int n_in,
                              void* d_out, int out_size) {
    const float* src    = (const float*)d_in[0];
    const float* emb_w  = (const float*)d_in[1];
    const float* emb_b  = (const float*)d_in[2];
    const float* qkv_w  = (const float*)d_in[3];
    const float* qkv_b  = (const float*)d_in[4];
    const float* out_w  = (const float*)d_in[5];
    const float* out_b  = (const float*)d_in[6];
    const float* ff1_w  = (const float*)d_in[7];
    const float* ff1_b  = (const float*)d_in[8];
    const float* ff2_w  = (const float*)d_in[9];
    const float* ff2_b  = (const float*)d_in[10];
    const float* ln1_g  = (const float*)d_in[11];
    const float* ln1_b  = (const float*)d_in[12];
    const float* ln2_g  = (const float*)d_in[13];
    const float* ln2_b  = (const float*)d_in[14];
    const float* lat_w  = (const float*)d_in[15];
    const float* lat_b  = (const float*)d_in[16];
    const float* head_w = (const float*)d_in[17];
    const float* head_b = (const float*)d_in[18];
    float* out = (float*)d_out;

    float *X, *PE, *P, *MEM;
    fp16 *QKVh, *Xh, *Oh, *Th, *Hh, *Wq, *Wo, *W1, *W2;
    cudaGetSymbolAddress((void**)&X,    g_X);
    cudaGetSymbolAddress((void**)&PE,   g_PE);
    cudaGetSymbolAddress((void**)&P,    g_LP);
    cudaGetSymbolAddress((void**)&MEM,  g_MEM);
    cudaGetSymbolAddress((void**)&QKVh, g_QKVh);
    cudaGetSymbolAddress((void**)&Xh,   g_Xh);
    cudaGetSymbolAddress((void**)&Oh,   g_Oh);
    cudaGetSymbolAddress((void**)&Th,   g_Th);
    cudaGetSymbolAddress((void**)&Hh,   g_Hh);
    cudaGetSymbolAddress((void**)&Wq,   g_Wq);
    cudaGetSymbolAddress((void**)&Wo,   g_Wo);
    cudaGetSymbolAddress((void**)&W1,   g_W1);
    cudaGetSymbolAddress((void**)&W2,   g_W2);

    cudaFuncSetAttribute(attn_mma,
                         cudaFuncAttributeMaxDynamicSharedMemorySize, ATTN_SMEM);
    cudaFuncSetAttribute(gemm_tc<1>,
                         cudaFuncAttributeMaxDynamicSharedMemorySize, GEMM_SMEM);
    cudaFuncSetAttribute(gemm_tc<2>,
                         cudaFuncAttributeMaxDynamicSharedMemorySize, GEMM_SMEM);

    // one-time-per-call weight converts (fp32 -> fp16), single launch
    {
        const int nq = NLAYER * 3 * DMODEL * DMODEL;
        const int no = NLAYER * DMODEL * DMODEL;
        const int n1 = NLAYER * DFF * DMODEL;
        const int n2 = NLAYER * DMODEL * DFF;
        const int ntot = nq + no + n1 + n2;
        conv4_kernel<<<(ntot + 255) / 256, 256>>>(qkv_w, Wq, nq, out_w, Wo, no,
                                                  ff1_w, W1, n1, ff2_w, W2, n2);
    }

    pe_kernel<<<SEQ, DMODEL>>>(PE);
    embed_kernel<<<NTOK, 128>>>(src, emb_w, emb_b, PE, X, Xh);

    for (int l = 0; l < NLAYER; l++) {
        gemm_tc<1><<<dim3(12, 128), 256, GEMM_SMEM>>>(
            Xh, Wq + (size_t)l * 1536 * DMODEL,
            qkv_b + l * 1536, QKVh, NTOK, 1536, DMODEL);
        attn_mma<<<dim3(NHEAD, BATCH), 256, ATTN_SMEM>>>(QKVh, Oh);
        gemm_tc<1><<<dim3(4, 128), 256, GEMM_SMEM>>>(
            Oh, Wo + (size_t)l * DMODEL * DMODEL,
            out_b + l * DMODEL, Th, NTOK, DMODEL, DMODEL);
        add_ln_kernel<<<NTOK, 256>>>(X, Th, ln1_g + l * DMODEL, ln1_b + l * DMODEL, Xh);
        gemm_tc<2><<<dim3(16, 128), 256, GEMM_SMEM>>>(
            Xh, W1 + (size_t)l * DFF * DMODEL,
            ff1_b + l * DFF, Hh, NTOK, DFF, DMODEL);
        gemm_tc<1><<<dim3(4, 128), 256, GEMM_SMEM>>>(
            Hh, W2 + (size_t)l * DMODEL * DFF,
            ff2_b + l * DMODEL, Th, NTOK, DMODEL, DFF);
        add_ln_kernel<<<NTOK, 256>>>(X, Th, ln2_g + l * DMODEL, ln2_b + l * DMODEL, Xh);
    }

    latent_partial<<<dim3(4, 64), 256>>>(X, lat_w, P);
    latent_reduce<<<64, 256>>>(P, lat_b, MEM);
    head_kernel<<<BATCH, 256>>>(MEM, head_w, head_b, out);
}